// round 1
// baseline (speedup 1.0000x reference)
#include <cuda_runtime.h>
#include <cuda_bf16.h>

#define N_NODES_MAX 100352
#define FEATS 128
#define NGRAPH 128
#define NCLASS 64

// ---------------- scratch (device globals; no allocation allowed) ----------
__device__ int   g_deg_out[N_NODES_MAX];
__device__ int   g_deg_in[N_NODES_MAX];
__device__ float g_h[(size_t)N_NODES_MAX * FEATS];     // projected+scaled feats
__device__ float g_agg[(size_t)N_NODES_MAX * FEATS];   // scatter destination
__device__ float g_hg[2 * NGRAPH * FEATS];             // per-graph sums (both branches)
__device__ int   g_cnt[2 * NGRAPH];                    // per-graph node counts

// ---------------- degrees ---------------------------------------------------
__global__ void degree_kernel(const int* __restrict__ src,
                              const int* __restrict__ dst, int nedges) {
    int e = blockIdx.x * blockDim.x + threadIdx.x;
    if (e < nedges) {
        atomicAdd(&g_deg_out[src[e]], 1);
        atomicAdd(&g_deg_in[dst[e]], 1);
    }
}

// ---------------- GEMM: g_h[r] = (deg_out[r]^-0.5) * (feat[r] @ W) ----------
// block = 256 threads, tile = 64 rows x 128 cols, W fully in smem.
__global__ void gemm_kernel(const float* __restrict__ feat,
                            const float* __restrict__ W, int nnodes) {
    extern __shared__ float sm[];
    float* sW = sm;                 // [128][128]
    float* sA = sm + 128 * 128;     // [64][128]

    const int tid  = threadIdx.x;
    const int row0 = blockIdx.x * 64;

    // load W (16384 floats = 4096 float4, 16 per thread)
    const float4* W4  = (const float4*)W;
    float4*       sW4 = (float4*)sW;
#pragma unroll
    for (int i = 0; i < 16; i++) sW4[tid + i * 256] = W4[tid + i * 256];

    // load A tile (64 rows x 32 float4 = 2048 float4, 8 per thread)
    const float4* F4  = (const float4*)feat;
    float4*       sA4 = (float4*)sA;
#pragma unroll
    for (int i = 0; i < 8; i++) {
        int idx = tid + i * 256;
        int r = idx >> 5, c = idx & 31;
        float4 v = make_float4(0.f, 0.f, 0.f, 0.f);
        if (row0 + r < nnodes) v = F4[(size_t)(row0 + r) * 32 + c];
        sA4[idx] = v;
    }
    __syncthreads();

    const int w = tid >> 5, lane = tid & 31;
    float4 acc[8];
#pragma unroll
    for (int i = 0; i < 8; i++) acc[i] = make_float4(0.f, 0.f, 0.f, 0.f);

    const float* sArow = sA + (w * 8) * 128;
#pragma unroll 4
    for (int k = 0; k < 128; k++) {
        float4 wv = *(const float4*)(sW + k * 128 + lane * 4);
#pragma unroll
        for (int i = 0; i < 8; i++) {
            float a = sArow[i * 128 + k];
            acc[i].x += a * wv.x;
            acc[i].y += a * wv.y;
            acc[i].z += a * wv.z;
            acc[i].w += a * wv.w;
        }
    }

#pragma unroll
    for (int i = 0; i < 8; i++) {
        int r = row0 + w * 8 + i;
        if (r < nnodes) {
            int dg = g_deg_out[r];
            float ds = rsqrtf((float)(dg > 1 ? dg : 1));
            float4 o = make_float4(acc[i].x * ds, acc[i].y * ds,
                                   acc[i].z * ds, acc[i].w * ds);
            *(float4*)&g_h[(size_t)r * 128 + lane * 4] = o;
        }
    }
}

// ---------------- edge scatter: agg[dst] += h[src] (warp per edge) ----------
__global__ void scatter_kernel(const int* __restrict__ src,
                               const int* __restrict__ dst, int nedges) {
    int t = blockIdx.x * blockDim.x + threadIdx.x;
    int e = t >> 5;
    if (e >= nedges) return;
    int lane = t & 31;
    int s = __ldg(src + e);
    int d = __ldg(dst + e);
    float4 v = *((const float4*)g_h + (size_t)s * 32 + lane);
    atomicAdd((float4*)g_agg + (size_t)d * 32 + lane, v);
}

// ---------------- per-node epilogue + graph pooling (warp per node) --------
__global__ void post_kernel(const int* __restrict__ gid,
                            const float* __restrict__ b,
                            float* __restrict__ hg, int* __restrict__ cnt,
                            int nnodes) {
    int t = blockIdx.x * blockDim.x + threadIdx.x;
    int n = t >> 5;
    if (n >= nnodes) return;
    int lane = t & 31;

    int dg = g_deg_in[n];
    float din = rsqrtf((float)(dg > 1 ? dg : 1));
    float4 a  = *((const float4*)g_agg + (size_t)n * 32 + lane);
    float4 bb = __ldg((const float4*)b + lane);
    float4 v = make_float4(a.x * din + bb.x, a.y * din + bb.y,
                           a.z * din + bb.z, a.w * din + bb.w);
    float ss = v.x * v.x + v.y * v.y + v.z * v.z + v.w * v.w;
#pragma unroll
    for (int o = 16; o; o >>= 1) ss += __shfl_xor_sync(0xffffffffu, ss, o);
    float inv = 1.f / fmaxf(sqrtf(ss), 1e-12f);

    v.x = 1.f / (1.f + __expf(-v.x * inv));
    v.y = 1.f / (1.f + __expf(-v.y * inv));
    v.z = 1.f / (1.f + __expf(-v.z * inv));
    v.w = 1.f / (1.f + __expf(-v.w * inv));

    int g = __ldg(gid + n);
    atomicAdd((float4*)hg + g * 32 + lane, v);
    if (lane == 0) atomicAdd(cnt + g, 1);
}

// ---------------- classifier + pairwise distance (block per graph) ---------
__global__ void final_kernel(const float* __restrict__ Wc,
                             const float* __restrict__ bc,
                             float* __restrict__ out) {
    int g = blockIdx.x, tid = threadIdx.x;  // 64 threads
    __shared__ float s1[128], s2[128];
    __shared__ float part[2];

    float c1 = fmaxf((float)g_cnt[g], 1.f);
    float c2 = fmaxf((float)g_cnt[NGRAPH + g], 1.f);
    for (int i = tid; i < 128; i += 64) {
        s1[i] = g_hg[g * 128 + i] / c1;
        s2[i] = g_hg[NGRAPH * 128 + g * 128 + i] / c2;
    }
    __syncthreads();

    float l1 = bc[tid], l2 = l1;
#pragma unroll 4
    for (int k = 0; k < 128; k++) {
        float w = Wc[k * NCLASS + tid];
        l1 += s1[k] * w;
        l2 += s2[k] * w;
    }
    float dd = l1 - l2 + 1e-6f;
    float sq = dd * dd;
#pragma unroll
    for (int o = 16; o; o >>= 1) sq += __shfl_xor_sync(0xffffffffu, sq, o);
    if ((tid & 31) == 0) part[tid >> 5] = sq;
    __syncthreads();
    if (tid == 0) out[g] = sqrtf(part[0] + part[1]);
}

// ---------------- launch ----------------------------------------------------
extern "C" void kernel_launch(void* const* d_in, const int* in_sizes, int n_in,
                              void* d_out, int out_size) {
    const float* feat[2] = {(const float*)d_in[0], (const float*)d_in[1]};
    const int*   src[2]  = {(const int*)d_in[2], (const int*)d_in[5]};
    const int*   dst[2]  = {(const int*)d_in[3], (const int*)d_in[6]};
    const int*   gid[2]  = {(const int*)d_in[4], (const int*)d_in[7]};
    const float* W  = (const float*)d_in[8];
    const float* b  = (const float*)d_in[9];
    const float* Wc = (const float*)d_in[10];
    const float* bc = (const float*)d_in[11];

    const int NN = in_sizes[0] / FEATS;       // 100000
    const int EE[2] = {in_sizes[2], in_sizes[5]};

    void *p_deg_out, *p_deg_in, *p_agg, *p_hg, *p_cnt;
    cudaGetSymbolAddress(&p_deg_out, g_deg_out);
    cudaGetSymbolAddress(&p_deg_in,  g_deg_in);
    cudaGetSymbolAddress(&p_agg,     g_agg);
    cudaGetSymbolAddress(&p_hg,      g_hg);
    cudaGetSymbolAddress(&p_cnt,     g_cnt);

    cudaFuncSetAttribute(gemm_kernel,
                         cudaFuncAttributeMaxDynamicSharedMemorySize, 96 * 1024);

    cudaMemsetAsync(p_hg, 0, 2 * NGRAPH * FEATS * sizeof(float));
    cudaMemsetAsync(p_cnt, 0, 2 * NGRAPH * sizeof(int));

    for (int br = 0; br < 2; br++) {
        const int E = EE[br];
        cudaMemsetAsync(p_deg_out, 0, NN * sizeof(int));
        cudaMemsetAsync(p_deg_in,  0, NN * sizeof(int));
        degree_kernel<<<(E + 255) / 256, 256>>>(src[br], dst[br], E);

        gemm_kernel<<<(NN + 63) / 64, 256, 96 * 1024>>>(feat[br], W, NN);

        cudaMemsetAsync(p_agg, 0, (size_t)NN * FEATS * sizeof(float));
        {
            long long threads = (long long)E * 32;
            int blocks = (int)((threads + 255) / 256);
            scatter_kernel<<<blocks, 256>>>(src[br], dst[br], E);
        }
        {
            long long threads = (long long)NN * 32;
            int blocks = (int)((threads + 255) / 256);
            post_kernel<<<blocks, 256>>>(gid[br], b,
                                         (float*)p_hg + br * NGRAPH * FEATS,
                                         (int*)p_cnt + br * NGRAPH, NN);
        }
    }
    final_kernel<<<NGRAPH, 64>>>(Wc, bc, (float*)d_out);
}

// round 2
// speedup vs baseline: 1.4759x; 1.4759x over previous
#include <cuda_runtime.h>
#include <cuda_bf16.h>

#define N_NODES_MAX 100352
#define N_EDGES_MAX 1605632
#define FEATS 128
#define NGRAPH 128
#define NCLASS 64

// ---------------- scratch (device globals; no allocation allowed) ----------
__device__ int   g_deg_out[N_NODES_MAX];
__device__ int   g_deg_in[N_NODES_MAX];
__device__ int   g_row_ptr[N_NODES_MAX];
__device__ int   g_cursor[N_NODES_MAX];
__device__ int   g_csr_src[N_EDGES_MAX];
__device__ float g_h[(size_t)N_NODES_MAX * FEATS];     // projected+scaled feats
__device__ float g_hg[2 * NGRAPH * FEATS];             // per-graph sums
__device__ int   g_cnt[2 * NGRAPH];                    // per-graph node counts

// ---------------- degrees ---------------------------------------------------
__global__ void degree_kernel(const int* __restrict__ src,
                              const int* __restrict__ dst, int nedges) {
    int e = blockIdx.x * blockDim.x + threadIdx.x;
    if (e < nedges) {
        atomicAdd(&g_deg_out[src[e]], 1);
        atomicAdd(&g_deg_in[dst[e]], 1);
    }
}

// ---------------- exclusive scan of deg_in -> row_ptr/cursor (1 block) ------
__global__ void scan_kernel(int nnodes) {
    __shared__ int warp_sums[32];
    __shared__ int s_running;
    int tid = threadIdx.x, lane = tid & 31, w = tid >> 5;
    if (tid == 0) s_running = 0;
    __syncthreads();
    for (int base = 0; base < nnodes; base += 1024) {
        int i = base + tid;
        int v = (i < nnodes) ? g_deg_in[i] : 0;
        int x = v;
#pragma unroll
        for (int o = 1; o < 32; o <<= 1) {
            int y = __shfl_up_sync(0xffffffffu, x, o);
            if (lane >= o) x += y;
        }
        if (lane == 31) warp_sums[w] = x;
        __syncthreads();
        if (w == 0) {
            int s = warp_sums[lane];
#pragma unroll
            for (int o = 1; o < 32; o <<= 1) {
                int y = __shfl_up_sync(0xffffffffu, s, o);
                if (lane >= o) s += y;
            }
            warp_sums[lane] = s;
        }
        __syncthreads();
        int warp_off = (w == 0) ? 0 : warp_sums[w - 1];
        int excl = s_running + warp_off + x - v;
        if (i < nnodes) { g_row_ptr[i] = excl; g_cursor[i] = excl; }
        __syncthreads();
        if (tid == 0) s_running += warp_sums[31];
        __syncthreads();
    }
}

// ---------------- CSR fill: bucket edges by dst ------------------------------
__global__ void fill_kernel(const int* __restrict__ src,
                            const int* __restrict__ dst, int nedges) {
    int e = blockIdx.x * blockDim.x + threadIdx.x;
    if (e < nedges) {
        int pos = atomicAdd(&g_cursor[dst[e]], 1);
        g_csr_src[pos] = src[e];
    }
}

// ---------------- tf32 MMA helper -------------------------------------------
__device__ __forceinline__ void mma_tf32(float4& c,
                                         unsigned a0, unsigned a1,
                                         unsigned a2, unsigned a3,
                                         unsigned b0, unsigned b1) {
    asm volatile(
        "mma.sync.aligned.m16n8k8.row.col.f32.tf32.tf32.f32 "
        "{%0,%1,%2,%3}, {%4,%5,%6,%7}, {%8,%9}, {%0,%1,%2,%3};\n"
        : "+f"(c.x), "+f"(c.y), "+f"(c.z), "+f"(c.w)
        : "r"(a0), "r"(a1), "r"(a2), "r"(a3), "r"(b0), "r"(b1));
}

// ---------------- GEMM (tf32 tensor core): g_h = ds * (feat @ W) ------------
// block = 256 threads (8 warps), tile 128 rows x 128 cols, K = 128.
__global__ void gemm_tc_kernel(const float* __restrict__ feat,
                               const float* __restrict__ W, int nnodes) {
    extern __shared__ float sm[];
    const int AS = 132;  // padded row stride (floats) -> conflict-free frags
    float* sA = sm;              // [128][AS] feat tile, row-major
    float* sB = sm + 128 * AS;   // [128][AS] W, row-major (k, n)

    const int tid  = threadIdx.x;
    const int row0 = blockIdx.x * 128;
    const float4* F4 = (const float4*)feat;
    const float4* W4 = (const float4*)W;

#pragma unroll
    for (int i = 0; i < 16; i++) {
        int idx = tid + i * 256;
        int r = idx >> 5, c4 = idx & 31;
        float4 av = make_float4(0.f, 0.f, 0.f, 0.f);
        if (row0 + r < nnodes) av = F4[(size_t)(row0 + r) * 32 + c4];
        *(float4*)(sA + r * AS + c4 * 4) = av;
        *(float4*)(sB + r * AS + c4 * 4) = W4[r * 32 + c4];
    }
    __syncthreads();

    const int w = tid >> 5, lane = tid & 31;
    const int gid8 = lane >> 2, tig = lane & 3;
    const int r0 = w * 16;

    float4 c[16];
#pragma unroll
    for (int j = 0; j < 16; j++) c[j] = make_float4(0.f, 0.f, 0.f, 0.f);

    const unsigned* uA = (const unsigned*)sA;
    const unsigned* uB = (const unsigned*)sB;

#pragma unroll
    for (int kk = 0; kk < 16; kk++) {
        int k0 = kk * 8;
        unsigned a0 = uA[(r0 + gid8) * AS + k0 + tig];
        unsigned a1 = uA[(r0 + gid8 + 8) * AS + k0 + tig];
        unsigned a2 = uA[(r0 + gid8) * AS + k0 + tig + 4];
        unsigned a3 = uA[(r0 + gid8 + 8) * AS + k0 + tig + 4];
#pragma unroll
        for (int j = 0; j < 16; j++) {
            unsigned b0 = uB[(k0 + tig) * AS + j * 8 + gid8];
            unsigned b1 = uB[(k0 + tig + 4) * AS + j * 8 + gid8];
            mma_tf32(c[j], a0, a1, a2, a3, b0, b1);
        }
    }

    int ra = row0 + r0 + gid8;
    int rb = ra + 8;
    bool va = ra < nnodes, vb = rb < nnodes;
    float dsa = 0.f, dsb = 0.f;
    if (va) { int d = g_deg_out[ra]; dsa = rsqrtf((float)(d > 1 ? d : 1)); }
    if (vb) { int d = g_deg_out[rb]; dsb = rsqrtf((float)(d > 1 ? d : 1)); }
#pragma unroll
    for (int j = 0; j < 16; j++) {
        int col = j * 8 + tig * 2;
        if (va) *(float2*)&g_h[(size_t)ra * 128 + col] =
                    make_float2(c[j].x * dsa, c[j].y * dsa);
        if (vb) *(float2*)&g_h[(size_t)rb * 128 + col] =
                    make_float2(c[j].z * dsb, c[j].w * dsb);
    }
}

// ---------------- gather-aggregate + fused epilogue (warp per node) ---------
__global__ void gather_kernel(const int* __restrict__ gid,
                              const float* __restrict__ bvec,
                              float* __restrict__ hg, int* __restrict__ cnt,
                              int nnodes) {
    int t = blockIdx.x * blockDim.x + threadIdx.x;
    int n = t >> 5;
    if (n >= nnodes) return;
    int lane = t & 31;

    int beg = g_row_ptr[n];
    int dg  = g_deg_in[n];
    int end = beg + dg;
    const float4* h4 = (const float4*)g_h;

    float4 acc = make_float4(0.f, 0.f, 0.f, 0.f);
    int e = beg;
    for (; e + 4 <= end; e += 4) {
        int s0 = __ldg(g_csr_src + e);
        int s1 = __ldg(g_csr_src + e + 1);
        int s2 = __ldg(g_csr_src + e + 2);
        int s3 = __ldg(g_csr_src + e + 3);
        float4 v0 = h4[(size_t)s0 * 32 + lane];
        float4 v1 = h4[(size_t)s1 * 32 + lane];
        float4 v2 = h4[(size_t)s2 * 32 + lane];
        float4 v3 = h4[(size_t)s3 * 32 + lane];
        acc.x += v0.x + v1.x + v2.x + v3.x;
        acc.y += v0.y + v1.y + v2.y + v3.y;
        acc.z += v0.z + v1.z + v2.z + v3.z;
        acc.w += v0.w + v1.w + v2.w + v3.w;
    }
    for (; e < end; e++) {
        int s = __ldg(g_csr_src + e);
        float4 v = h4[(size_t)s * 32 + lane];
        acc.x += v.x; acc.y += v.y; acc.z += v.z; acc.w += v.w;
    }

    float din = rsqrtf((float)(dg > 1 ? dg : 1));
    float4 bb = __ldg((const float4*)bvec + lane);
    float4 v = make_float4(acc.x * din + bb.x, acc.y * din + bb.y,
                           acc.z * din + bb.z, acc.w * din + bb.w);
    float ss = v.x * v.x + v.y * v.y + v.z * v.z + v.w * v.w;
#pragma unroll
    for (int o = 16; o; o >>= 1) ss += __shfl_xor_sync(0xffffffffu, ss, o);
    float inv = 1.f / fmaxf(sqrtf(ss), 1e-12f);

    v.x = 1.f / (1.f + __expf(-v.x * inv));
    v.y = 1.f / (1.f + __expf(-v.y * inv));
    v.z = 1.f / (1.f + __expf(-v.z * inv));
    v.w = 1.f / (1.f + __expf(-v.w * inv));

    int g = __ldg(gid + n);
    atomicAdd((float4*)hg + g * 32 + lane, v);
    if (lane == 0) atomicAdd(cnt + g, 1);
}

// ---------------- classifier + pairwise distance (block per graph) ---------
__global__ void final_kernel(const float* __restrict__ Wc,
                             const float* __restrict__ bc,
                             float* __restrict__ out) {
    int g = blockIdx.x, tid = threadIdx.x;  // 64 threads
    __shared__ float s1[128], s2[128];
    __shared__ float part[2];

    float c1 = fmaxf((float)g_cnt[g], 1.f);
    float c2 = fmaxf((float)g_cnt[NGRAPH + g], 1.f);
    for (int i = tid; i < 128; i += 64) {
        s1[i] = g_hg[g * 128 + i] / c1;
        s2[i] = g_hg[NGRAPH * 128 + g * 128 + i] / c2;
    }
    __syncthreads();

    float l1 = bc[tid], l2 = l1;
#pragma unroll 4
    for (int k = 0; k < 128; k++) {
        float w = Wc[k * NCLASS + tid];
        l1 += s1[k] * w;
        l2 += s2[k] * w;
    }
    float dd = l1 - l2 + 1e-6f;
    float sq = dd * dd;
#pragma unroll
    for (int o = 16; o; o >>= 1) sq += __shfl_xor_sync(0xffffffffu, sq, o);
    if ((tid & 31) == 0) part[tid >> 5] = sq;
    __syncthreads();
    if (tid == 0) out[g] = sqrtf(part[0] + part[1]);
}

// ---------------- launch ----------------------------------------------------
extern "C" void kernel_launch(void* const* d_in, const int* in_sizes, int n_in,
                              void* d_out, int out_size) {
    const float* feat[2] = {(const float*)d_in[0], (const float*)d_in[1]};
    const int*   src[2]  = {(const int*)d_in[2], (const int*)d_in[5]};
    const int*   dst[2]  = {(const int*)d_in[3], (const int*)d_in[6]};
    const int*   gid[2]  = {(const int*)d_in[4], (const int*)d_in[7]};
    const float* W  = (const float*)d_in[8];
    const float* b  = (const float*)d_in[9];
    const float* Wc = (const float*)d_in[10];
    const float* bc = (const float*)d_in[11];

    const int NN = in_sizes[0] / FEATS;       // 100000
    const int EE[2] = {in_sizes[2], in_sizes[5]};

    void *p_deg_out, *p_deg_in, *p_hg, *p_cnt;
    cudaGetSymbolAddress(&p_deg_out, g_deg_out);
    cudaGetSymbolAddress(&p_deg_in,  g_deg_in);
    cudaGetSymbolAddress(&p_hg,      g_hg);
    cudaGetSymbolAddress(&p_cnt,     g_cnt);

    const int SMEM = 128 * 132 * 2 * 4;  // 135168 B
    cudaFuncSetAttribute(gemm_tc_kernel,
                         cudaFuncAttributeMaxDynamicSharedMemorySize, SMEM);

    cudaMemsetAsync(p_hg, 0, 2 * NGRAPH * FEATS * sizeof(float));
    cudaMemsetAsync(p_cnt, 0, 2 * NGRAPH * sizeof(int));

    for (int br = 0; br < 2; br++) {
        const int E = EE[br];
        cudaMemsetAsync(p_deg_out, 0, NN * sizeof(int));
        cudaMemsetAsync(p_deg_in,  0, NN * sizeof(int));
        degree_kernel<<<(E + 255) / 256, 256>>>(src[br], dst[br], E);
        scan_kernel<<<1, 1024>>>(NN);
        fill_kernel<<<(E + 255) / 256, 256>>>(src[br], dst[br], E);

        gemm_tc_kernel<<<(NN + 127) / 128, 256, SMEM>>>(feat[br], W, NN);

        {
            long long threads = (long long)NN * 32;
            int blocks = (int)((threads + 255) / 256);
            gather_kernel<<<blocks, 256>>>(gid[br], b,
                                           (float*)p_hg + br * NGRAPH * FEATS,
                                           (int*)p_cnt + br * NGRAPH, NN);
        }
    }
    final_kernel<<<NGRAPH, 64>>>(Wc, bc, (float*)d_out);
}

// round 4
// speedup vs baseline: 2.4954x; 1.6907x over previous
#include <cuda_runtime.h>
#include <cuda_fp16.h>
#include <cuda_bf16.h>

#define N_NODES_MAX 100352
#define N_EDGES_MAX 1605632
#define FEATS 128
#define NGRAPH 128
#define NCLASS 64
#define SCAN_TILE 4096

// ---------------- scratch (device globals) ----------------------------------
__device__ int    g_deg_out[2][N_NODES_MAX];
__device__ int    g_deg_in[2][N_NODES_MAX];
__device__ int    g_row_ptr[2][N_NODES_MAX];
__device__ int    g_cursor[2][N_NODES_MAX];
__device__ int    g_csr_src[2][N_EDGES_MAX];
__device__ __half g_h[2][(size_t)N_NODES_MAX * FEATS];
__device__ __half g_WT[FEATS * FEATS];           // W^T in fp16: [n][k]
__device__ float  g_hg[2 * NGRAPH * FEATS];
__device__ int    g_cnt[2 * NGRAPH];
__device__ int    g_part[2 * 64];
__device__ int    g_part_scan[2 * 64];

// ---------------- W transpose + fp16 convert --------------------------------
__global__ void prep_wt_kernel(const float* __restrict__ W) {
    int t = blockIdx.x * blockDim.x + threadIdx.x;   // 16384
    int k = t >> 7, n = t & 127;
    g_WT[n * 128 + k] = __float2half_rn(W[k * 128 + n]);
}

// ---------------- degrees, both branches ------------------------------------
__global__ void degree2_kernel(const int* __restrict__ s1, const int* __restrict__ d1, int E1,
                               const int* __restrict__ s2, const int* __restrict__ d2, int E2) {
    int e = blockIdx.x * blockDim.x + threadIdx.x;
    if (e < E1) {
        atomicAdd(&g_deg_out[0][s1[e]], 1);
        atomicAdd(&g_deg_in[0][d1[e]], 1);
    } else if (e < E1 + E2) {
        int i = e - E1;
        atomicAdd(&g_deg_out[1][s2[i]], 1);
        atomicAdd(&g_deg_in[1][d2[i]], 1);
    }
}

// ---------------- scan phase 1: per-tile sums --------------------------------
__global__ void reduce_kernel(int nnodes) {
    int br = blockIdx.y, blk = blockIdx.x;
    int i = blk * SCAN_TILE + threadIdx.x * 4;
    int lane = threadIdx.x & 31, w = threadIdx.x >> 5;
    int s = 0;
    if (i + 3 < nnodes) {
        int4 v = *(const int4*)&g_deg_in[br][i];
        s = v.x + v.y + v.z + v.w;
    } else {
        for (int k = 0; k < 4; k++) if (i + k < nnodes) s += g_deg_in[br][i + k];
    }
#pragma unroll
    for (int o = 16; o; o >>= 1) s += __shfl_xor_sync(0xffffffffu, s, o);
    __shared__ int ws[32];
    if (lane == 0) ws[w] = s;
    __syncthreads();
    if (threadIdx.x < 32) {
        int t = ws[threadIdx.x];
#pragma unroll
        for (int o = 16; o; o >>= 1) t += __shfl_xor_sync(0xffffffffu, t, o);
        if (threadIdx.x == 0) g_part[br * 64 + blk] = t;
    }
}

// ---------------- scan phase 2: scan tile sums (1 block, warp per branch) ----
__global__ void scan_part_kernel(int nblk) {
    int br = threadIdx.x >> 5, lane = threadIdx.x & 31;
    if (br >= 2) return;
    int v = (lane < nblk) ? g_part[br * 64 + lane] : 0;
    int x = v;
#pragma unroll
    for (int o = 1; o < 32; o <<= 1) {
        int y = __shfl_up_sync(0xffffffffu, x, o);
        if (lane >= o) x += y;
    }
    g_part_scan[br * 64 + lane] = x - v;
}

// ---------------- scan phase 3: local rescan -> row_ptr & cursor -------------
__global__ void local_scan_kernel(int nnodes) {
    int br = blockIdx.y, blk = blockIdx.x;
    int i = blk * SCAN_TILE + threadIdx.x * 4;
    int lane = threadIdx.x & 31, w = threadIdx.x >> 5;
    int4 v = make_int4(0, 0, 0, 0);
    if (i + 3 < nnodes) v = *(const int4*)&g_deg_in[br][i];
    else {
        if (i     < nnodes) v.x = g_deg_in[br][i];
        if (i + 1 < nnodes) v.y = g_deg_in[br][i + 1];
        if (i + 2 < nnodes) v.z = g_deg_in[br][i + 2];
    }
    int s0 = v.x, s1 = s0 + v.y, s2 = s1 + v.z, s3 = s2 + v.w;
    int x = s3;
#pragma unroll
    for (int o = 1; o < 32; o <<= 1) {
        int y = __shfl_up_sync(0xffffffffu, x, o);
        if (lane >= o) x += y;
    }
    __shared__ int ws[32];
    if (lane == 31) ws[w] = x;
    __syncthreads();
    if (w == 0) {
        int t = ws[lane];
#pragma unroll
        for (int o = 1; o < 32; o <<= 1) {
            int y = __shfl_up_sync(0xffffffffu, t, o);
            if (lane >= o) t += y;
        }
        ws[lane] = t;
    }
    __syncthreads();
    int base = g_part_scan[br * 64 + blk] + (w ? ws[w - 1] : 0) + (x - s3);
    int4 e = make_int4(base, base + s0, base + s1, base + s2);
    if (i + 3 < nnodes) {
        *(int4*)&g_row_ptr[br][i] = e;
        *(int4*)&g_cursor[br][i]  = e;
    } else {
        if (i     < nnodes) { g_row_ptr[br][i]     = e.x; g_cursor[br][i]     = e.x; }
        if (i + 1 < nnodes) { g_row_ptr[br][i + 1] = e.y; g_cursor[br][i + 1] = e.y; }
        if (i + 2 < nnodes) { g_row_ptr[br][i + 2] = e.z; g_cursor[br][i + 2] = e.z; }
    }
}

// ---------------- CSR fill, both branches ------------------------------------
__global__ void fill2_kernel(const int* __restrict__ s1, const int* __restrict__ d1, int E1,
                             const int* __restrict__ s2, const int* __restrict__ d2, int E2) {
    int e = blockIdx.x * blockDim.x + threadIdx.x;
    if (e < E1) {
        int pos = atomicAdd(&g_cursor[0][d1[e]], 1);
        g_csr_src[0][pos] = s1[e];
    } else if (e < E1 + E2) {
        int i = e - E1;
        int pos = atomicAdd(&g_cursor[1][d2[i]], 1);
        g_csr_src[1][pos] = s2[i];
    }
}

// ---------------- fp16 MMA helper --------------------------------------------
__device__ __forceinline__ void mma_f16(float4& c,
                                        unsigned a0, unsigned a1,
                                        unsigned a2, unsigned a3,
                                        unsigned b0, unsigned b1) {
    asm volatile(
        "mma.sync.aligned.m16n8k16.row.col.f32.f16.f16.f32 "
        "{%0,%1,%2,%3}, {%4,%5,%6,%7}, {%8,%9}, {%0,%1,%2,%3};\n"
        : "+f"(c.x), "+f"(c.y), "+f"(c.z), "+f"(c.w)
        : "r"(a0), "r"(a1), "r"(a2), "r"(a3), "r"(b0), "r"(b1));
}

// ---------------- GEMM (fp16 HMMA): g_h[br] = ds * (feat @ W), fp16 out ------
// block = 256 threads (8 warps), tile 128 rows x 128 cols, K = 128, grid.y=branch
#define AS 136  // half stride per smem row (272B) -> conflict-free
__global__ void __launch_bounds__(256, 2)
gemm_fp16_kernel(const float* __restrict__ feat0, const float* __restrict__ feat1,
                 int nnodes) {
    extern __shared__ __half sm[];
    __half* sA  = sm;              // [128][AS]  feat tile (fp16), row-major
    __half* sBt = sm + 128 * AS;   // [128][AS]  W^T: [n][k]

    const int br   = blockIdx.y;
    const float* feat = br ? feat1 : feat0;
    const int tid  = threadIdx.x;
    const int row0 = blockIdx.x * 128;
    const float4* F4  = (const float4*)feat;
    const uint4*  WT4 = (const uint4*)g_WT;

#pragma unroll
    for (int i = 0; i < 8; i++) {
        int idx = tid + i * 256;          // 2048 uint4 total
        int r = idx >> 4, c = idx & 15;   // row, uint4-col (8 halves)
        float4 f0 = make_float4(0.f, 0.f, 0.f, 0.f), f1 = f0;
        if (row0 + r < nnodes) {
            f0 = F4[(size_t)(row0 + r) * 32 + 2 * c];
            f1 = F4[(size_t)(row0 + r) * 32 + 2 * c + 1];
        }
        union { __half2 h[4]; uint4 u; } p;
        p.h[0] = __floats2half2_rn(f0.x, f0.y);
        p.h[1] = __floats2half2_rn(f0.z, f0.w);
        p.h[2] = __floats2half2_rn(f1.x, f1.y);
        p.h[3] = __floats2half2_rn(f1.z, f1.w);
        *(uint4*)&sA[r * AS + c * 8] = p.u;
        *(uint4*)&sBt[r * AS + c * 8] = WT4[idx];
    }
    __syncthreads();

    const int w = tid >> 5, lane = tid & 31;
    const int gid8 = lane >> 2, tig = lane & 3;
    const int r0 = w * 16;

    float4 c[16];
#pragma unroll
    for (int j = 0; j < 16; j++) c[j] = make_float4(0.f, 0.f, 0.f, 0.f);

#pragma unroll
    for (int kk = 0; kk < 8; kk++) {
        int k0 = kk * 16;
        unsigned a0 = *(const unsigned*)&sA[(r0 + gid8) * AS + k0 + 2 * tig];
        unsigned a1 = *(const unsigned*)&sA[(r0 + gid8 + 8) * AS + k0 + 2 * tig];
        unsigned a2 = *(const unsigned*)&sA[(r0 + gid8) * AS + k0 + 8 + 2 * tig];
        unsigned a3 = *(const unsigned*)&sA[(r0 + gid8 + 8) * AS + k0 + 8 + 2 * tig];
#pragma unroll
        for (int j = 0; j < 16; j++) {
            unsigned b0 = *(const unsigned*)&sBt[(j * 8 + gid8) * AS + k0 + 2 * tig];
            unsigned b1 = *(const unsigned*)&sBt[(j * 8 + gid8) * AS + k0 + 8 + 2 * tig];
            mma_f16(c[j], a0, a1, a2, a3, b0, b1);
        }
    }

    int ra = row0 + r0 + gid8;
    int rb = ra + 8;
    bool va = ra < nnodes, vb = rb < nnodes;
    float dsa = 0.f, dsb = 0.f;
    if (va) { int d = g_deg_out[br][ra]; dsa = rsqrtf((float)(d > 1 ? d : 1)); }
    if (vb) { int d = g_deg_out[br][rb]; dsb = rsqrtf((float)(d > 1 ? d : 1)); }
    unsigned* H = (unsigned*)g_h[br];
#pragma unroll
    for (int j = 0; j < 16; j++) {
        int colw = j * 4 + tig;  // half2 index within row (64 per row)
        if (va) {
            __half2 o = __floats2half2_rn(c[j].x * dsa, c[j].y * dsa);
            H[(size_t)ra * 64 + colw] = *(unsigned*)&o;
        }
        if (vb) {
            __half2 o = __floats2half2_rn(c[j].z * dsb, c[j].w * dsb);
            H[(size_t)rb * 64 + colw] = *(unsigned*)&o;
        }
    }
}

// ---------------- gather-aggregate + fused epilogue (warp per node) ----------
__global__ void gather2_kernel(const int* __restrict__ gid0,
                               const int* __restrict__ gid1,
                               const float* __restrict__ bvec, int nnodes) {
    int t = blockIdx.x * blockDim.x + threadIdx.x;
    int n2 = t >> 5;
    if (n2 >= 2 * nnodes) return;
    int br = (n2 >= nnodes) ? 1 : 0;
    int n = n2 - br * nnodes;
    int lane = t & 31;

    int beg = g_row_ptr[br][n];
    int dg  = g_deg_in[br][n];
    int end = beg + dg;
    const uint2* H2 = (const uint2*)g_h[br];   // 8B per lane = 4 halves
    const int* csr = g_csr_src[br];

    float4 acc = make_float4(0.f, 0.f, 0.f, 0.f);
    int e = beg;
    for (; e + 4 <= end; e += 4) {
        int s0 = __ldg(csr + e);
        int s1 = __ldg(csr + e + 1);
        int s2 = __ldg(csr + e + 2);
        int s3 = __ldg(csr + e + 3);
        uint2 u0 = H2[(size_t)s0 * 32 + lane];
        uint2 u1 = H2[(size_t)s1 * 32 + lane];
        uint2 u2 = H2[(size_t)s2 * 32 + lane];
        uint2 u3 = H2[(size_t)s3 * 32 + lane];
        float2 f;
        f = __half22float2(*(__half2*)&u0.x); acc.x += f.x; acc.y += f.y;
        f = __half22float2(*(__half2*)&u0.y); acc.z += f.x; acc.w += f.y;
        f = __half22float2(*(__half2*)&u1.x); acc.x += f.x; acc.y += f.y;
        f = __half22float2(*(__half2*)&u1.y); acc.z += f.x; acc.w += f.y;
        f = __half22float2(*(__half2*)&u2.x); acc.x += f.x; acc.y += f.y;
        f = __half22float2(*(__half2*)&u2.y); acc.z += f.x; acc.w += f.y;
        f = __half22float2(*(__half2*)&u3.x); acc.x += f.x; acc.y += f.y;
        f = __half22float2(*(__half2*)&u3.y); acc.z += f.x; acc.w += f.y;
    }
    for (; e < end; e++) {
        int s = __ldg(csr + e);
        uint2 u = H2[(size_t)s * 32 + lane];
        float2 f;
        f = __half22float2(*(__half2*)&u.x); acc.x += f.x; acc.y += f.y;
        f = __half22float2(*(__half2*)&u.y); acc.z += f.x; acc.w += f.y;
    }

    float din = rsqrtf((float)(dg > 1 ? dg : 1));
    float4 bb = __ldg((const float4*)bvec + lane);
    float4 v = make_float4(acc.x * din + bb.x, acc.y * din + bb.y,
                           acc.z * din + bb.z, acc.w * din + bb.w);
    float ss = v.x * v.x + v.y * v.y + v.z * v.z + v.w * v.w;
#pragma unroll
    for (int o = 16; o; o >>= 1) ss += __shfl_xor_sync(0xffffffffu, ss, o);
    float inv = 1.f / fmaxf(sqrtf(ss), 1e-12f);

    v.x = 1.f / (1.f + __expf(-v.x * inv));
    v.y = 1.f / (1.f + __expf(-v.y * inv));
    v.z = 1.f / (1.f + __expf(-v.z * inv));
    v.w = 1.f / (1.f + __expf(-v.w * inv));

    const int* gid = br ? gid1 : gid0;
    int g = __ldg(gid + n);
    atomicAdd((float4*)g_hg + (br * NGRAPH + g) * 32 + lane, v);
    if (lane == 0) atomicAdd(&g_cnt[br * NGRAPH + g], 1);
}

// ---------------- classifier + pairwise distance (block per graph) -----------
__global__ void final_kernel(const float* __restrict__ Wc,
                             const float* __restrict__ bc,
                             float* __restrict__ out) {
    int g = blockIdx.x, tid = threadIdx.x;  // 64 threads
    __shared__ float s1[128], s2[128];
    __shared__ float part[2];

    float c1 = fmaxf((float)g_cnt[g], 1.f);
    float c2 = fmaxf((float)g_cnt[NGRAPH + g], 1.f);
    for (int i = tid; i < 128; i += 64) {
        s1[i] = g_hg[g * 128 + i] / c1;
        s2[i] = g_hg[NGRAPH * 128 + g * 128 + i] / c2;
    }
    __syncthreads();

    float l1 = bc[tid], l2 = l1;
#pragma unroll 4
    for (int k = 0; k < 128; k++) {
        float w = Wc[k * NCLASS + tid];
        l1 += s1[k] * w;
        l2 += s2[k] * w;
    }
    float dd = l1 - l2 + 1e-6f;
    float sq = dd * dd;
#pragma unroll
    for (int o = 16; o; o >>= 1) sq += __shfl_xor_sync(0xffffffffu, sq, o);
    if ((tid & 31) == 0) part[tid >> 5] = sq;
    __syncthreads();
    if (tid == 0) out[g] = sqrtf(part[0] + part[1]);
}

// ---------------- launch ------------------------------------------------------
extern "C" void kernel_launch(void* const* d_in, const int* in_sizes, int n_in,
                              void* d_out, int out_size) {
    const float* feat1 = (const float*)d_in[0];
    const float* feat2 = (const float*)d_in[1];
    const int* src1 = (const int*)d_in[2];
    const int* dst1 = (const int*)d_in[3];
    const int* gid1 = (const int*)d_in[4];
    const int* src2 = (const int*)d_in[5];
    const int* dst2 = (const int*)d_in[6];
    const int* gid2 = (const int*)d_in[7];
    const float* W  = (const float*)d_in[8];
    const float* b  = (const float*)d_in[9];
    const float* Wc = (const float*)d_in[10];
    const float* bc = (const float*)d_in[11];

    const int NN = in_sizes[0] / FEATS;
    const int E1 = in_sizes[2], E2 = in_sizes[5];
    const int nblk = (NN + SCAN_TILE - 1) / SCAN_TILE;

    void *p_deg_out, *p_deg_in, *p_hg, *p_cnt;
    cudaGetSymbolAddress(&p_deg_out, g_deg_out);
    cudaGetSymbolAddress(&p_deg_in,  g_deg_in);
    cudaGetSymbolAddress(&p_hg,      g_hg);
    cudaGetSymbolAddress(&p_cnt,     g_cnt);

    const int SMEM = 2 * 128 * AS * (int)sizeof(__half);  // 69632
    cudaFuncSetAttribute(gemm_fp16_kernel,
                         cudaFuncAttributeMaxDynamicSharedMemorySize, SMEM);

    cudaMemsetAsync(p_hg, 0, 2 * NGRAPH * FEATS * sizeof(float));
    cudaMemsetAsync(p_cnt, 0, 2 * NGRAPH * sizeof(int));
    cudaMemsetAsync(p_deg_out, 0, 2 * N_NODES_MAX * sizeof(int));
    cudaMemsetAsync(p_deg_in,  0, 2 * N_NODES_MAX * sizeof(int));

    prep_wt_kernel<<<64, 256>>>(W);
    degree2_kernel<<<(E1 + E2 + 255) / 256, 256>>>(src1, dst1, E1, src2, dst2, E2);

    {
        dim3 grid(nblk, 2);
        reduce_kernel<<<grid, 1024>>>(NN);
        scan_part_kernel<<<1, 64>>>(nblk);
        local_scan_kernel<<<grid, 1024>>>(NN);
    }
    fill2_kernel<<<(E1 + E2 + 255) / 256, 256>>>(src1, dst1, E1, src2, dst2, E2);

    {
        dim3 grid((NN + 127) / 128, 2);
        gemm_fp16_kernel<<<grid, 256, SMEM>>>(feat1, feat2, NN);
    }
    {
        long long threads = (long long)2 * NN * 32;
        int blocks = (int)((threads + 255) / 256);
        gather2_kernel<<<blocks, 256>>>(gid1, gid2, b, NN);
    }
    final_kernel<<<NGRAPH, 64>>>(Wc, bc, (float*)d_out);
}